// round 1
// baseline (speedup 1.0000x reference)
#include <cuda_runtime.h>
#include <math.h>

#define W_DIM 512
#define F_DIM 512
#define FIN   1024
#define NH    8
#define DH    64
#define NLAYER 12
#define EPSV  1e-5f

// ---------------- scratch (device globals; no allocations allowed) ----------
__device__ float g_e  [4 * 512 * 512];
__device__ float g_h  [4 * 512 * 512];
__device__ float g_q  [4 * 512 * 512];
__device__ float g_k  [4 * 512 * 512];
__device__ float g_v  [4 * 512 * 512];
__device__ float g_tmp[4 * 512 * 512];
__device__ float g_big[4 * 2048 * 512];
__device__ float g_s  [32 * 512 * 512];

// ---------------- batched GEMM: C[bc] = Wt[c] @ X[bc] (+res, +sqrelu) -------
// Wt: (M,K) row-major per channel c = bc&1 ; X: (K,N) row-major per bc ; N=512
template<bool SQRELU, bool HASRES>
__global__ void __launch_bounds__(256) gemm_nn(
    const float* __restrict__ A, const float* __restrict__ B,
    const float* __restrict__ Res, float* __restrict__ Cout,
    int M, int N, int K)
{
    int bc = blockIdx.z;
    const float* Ab = A + (size_t)(bc & 1) * M * K;
    const float* Bb = B + (size_t)bc * K * N;
    float* Cb = Cout + (size_t)bc * M * N;
    const float* Rb = HASRES ? (Res + (size_t)bc * M * N) : nullptr;

    __shared__ float As[64][17];
    __shared__ float Bs[16][64];

    int tid = threadIdx.x;
    int tx = tid & 15, ty = tid >> 4;
    int m0 = blockIdx.y * 64, n0 = blockIdx.x * 64;

    float acc[4][4] = {};

    for (int k0 = 0; k0 < K; k0 += 16) {
        #pragma unroll
        for (int i = 0; i < 4; i++) {
            int idx = tid + i * 256;
            int mr = idx >> 4, kc = idx & 15;
            As[mr][kc] = Ab[(size_t)(m0 + mr) * K + k0 + kc];
        }
        #pragma unroll
        for (int i = 0; i < 4; i++) {
            int idx = tid + i * 256;
            int kr = idx >> 6, nc = idx & 63;
            Bs[kr][nc] = Bb[(size_t)(k0 + kr) * N + n0 + nc];
        }
        __syncthreads();
        #pragma unroll
        for (int kk = 0; kk < 16; kk++) {
            float a0 = As[ty * 4 + 0][kk];
            float a1 = As[ty * 4 + 1][kk];
            float a2 = As[ty * 4 + 2][kk];
            float a3 = As[ty * 4 + 3][kk];
            float4 b = *reinterpret_cast<const float4*>(&Bs[kk][tx * 4]);
            acc[0][0] += a0 * b.x; acc[0][1] += a0 * b.y; acc[0][2] += a0 * b.z; acc[0][3] += a0 * b.w;
            acc[1][0] += a1 * b.x; acc[1][1] += a1 * b.y; acc[1][2] += a1 * b.z; acc[1][3] += a1 * b.w;
            acc[2][0] += a2 * b.x; acc[2][1] += a2 * b.y; acc[2][2] += a2 * b.z; acc[2][3] += a2 * b.w;
            acc[3][0] += a3 * b.x; acc[3][1] += a3 * b.y; acc[3][2] += a3 * b.z; acc[3][3] += a3 * b.w;
        }
        __syncthreads();
    }

    #pragma unroll
    for (int i = 0; i < 4; i++) {
        int m = m0 + ty * 4 + i;
        #pragma unroll
        for (int j = 0; j < 4; j++) {
            int n = n0 + tx * 4 + j;
            float v = acc[i][j];
            if (SQRELU) { float r = fmaxf(v, 0.f); v = r * r; }
            if (HASRES) v += Rb[(size_t)m * N + n];
            Cb[(size_t)m * N + n] = v;
        }
    }
}

// ---------------- channel mix: Y[b,d,f,w] = dw[d,0]X[b,0,f,w]+dw[d,1]X[b,1,f,w]
template<bool SQRELU, bool HASADD>
__global__ void __launch_bounds__(256) mix_k(
    const float* __restrict__ X, const float* __restrict__ dw,
    const float* __restrict__ Add, float* __restrict__ Y, int Fd)
{
    int idx = blockIdx.x * 256 + threadIdx.x;
    int total = 4 * Fd * W_DIM;
    if (idx >= total) return;
    int w = idx & 511;
    int f = (idx >> 9) % Fd;
    int bd = idx / (512 * Fd);
    int b = bd >> 1, d = bd & 1;
    size_t base = ((size_t)(b * 2) * Fd + f) * W_DIM + w;
    float v = dw[d * 2 + 0] * X[base] + dw[d * 2 + 1] * X[base + (size_t)Fd * W_DIM];
    if (SQRELU) { float r = fmaxf(v, 0.f); v = r * r; }
    if (HASADD) v += Add[idx];
    Y[idx] = v;
}

// ---------------- channel mix + RoPE (F=512) --------------------------------
__global__ void __launch_bounds__(256) mix_rope_k(
    const float* __restrict__ X, const float* __restrict__ dw,
    float* __restrict__ Y)
{
    int idx = blockIdx.x * 256 + threadIdx.x;  // 4 * 256 * 512 = 524288 pairs
    int w  = idx & 511;
    int fp = (idx >> 9) & 255;
    int bd = idx >> 17;
    int b = bd >> 1, d = bd & 1;
    int f0 = fp * 2;
    size_t b0 = ((size_t)(b * 2) * F_DIM + f0) * W_DIM + w;
    float d0 = dw[d * 2 + 0], d1 = dw[d * 2 + 1];
    float v0 = d0 * X[b0]          + d1 * X[b0 + (size_t)F_DIM * W_DIM];
    float v1 = d0 * X[b0 + W_DIM]  + d1 * X[b0 + W_DIM + (size_t)F_DIM * W_DIM];
    int i = fp & 31;                       // pair index within head (dh=64)
    float inv = powf(10000.f, -(float)(2 * i) / 64.f);
    float ang = (float)w * inv;
    float sn, cs;
    sincosf(ang, &sn, &cs);
    size_t o0 = ((size_t)bd * F_DIM + f0) * W_DIM + w;
    Y[o0]          = v0 * cs - v1 * sn;
    Y[o0 + W_DIM]  = v1 * cs + v0 * sn;
}

// ---------------- frame_norm: LN over F per (b,c,w) --------------------------
__global__ void frame_norm_k(
    const float* __restrict__ X, const float* __restrict__ gw,
    const float* __restrict__ gb, float* __restrict__ Y)
{
    int bc = blockIdx.y;
    int c = bc & 1;
    int tx = threadIdx.x, ty = threadIdx.y;
    int w = blockIdx.x * 32 + tx;
    const float* Xb = X + (size_t)bc * F_DIM * W_DIM;
    float* Yb = Y + (size_t)bc * F_DIM * W_DIM;

    float sum = 0.f, sq = 0.f;
    for (int f = ty; f < F_DIM; f += 8) {
        float v = Xb[(size_t)f * W_DIM + w];
        sum += v; sq += v * v;
    }
    __shared__ float ss[8][33], s2[8][33];
    __shared__ float smu[32], srs[32];
    ss[ty][tx] = sum; s2[ty][tx] = sq;
    __syncthreads();
    if (ty == 0) {
        for (int r = 1; r < 8; r++) { sum += ss[r][tx]; sq += s2[r][tx]; }
        float mu = sum * (1.f / 512.f);
        float var = sq * (1.f / 512.f) - mu * mu;
        smu[tx] = mu;
        srs[tx] = rsqrtf(var + EPSV);
    }
    __syncthreads();
    float mu = smu[tx], rs = srs[tx];
    for (int f = ty; f < F_DIM; f += 8) {
        float v = Xb[(size_t)f * W_DIM + w];
        Yb[(size_t)f * W_DIM + w] = (v - mu) * rs * gw[c * F_DIM + f] + gb[c * F_DIM + f];
    }
}

// ---------------- attention scores: S[q,k] = scale * sum_d Q[d,q]K[d,k] ------
__global__ void __launch_bounds__(256) attn_scores_k(
    const float* __restrict__ Q, const float* __restrict__ Kt,
    float* __restrict__ S)
{
    int batch = blockIdx.z;                    // 32 = bc*8 + h
    int bc = batch >> 3, h = batch & 7;
    const float* Qb = Q + ((size_t)bc * F_DIM + h * DH) * W_DIM;
    const float* Kb = Kt + ((size_t)bc * F_DIM + h * DH) * W_DIM;
    float* Sb = S + (size_t)batch * W_DIM * W_DIM;

    __shared__ float Qs[16][64];
    __shared__ float Ks[16][64];
    int tid = threadIdx.x;
    int tx = tid & 15, ty = tid >> 4;
    int q0 = blockIdx.y * 64, k0 = blockIdx.x * 64;
    float acc[4][4] = {};

    for (int d0 = 0; d0 < DH; d0 += 16) {
        #pragma unroll
        for (int i = 0; i < 4; i++) {
            int idx = tid + i * 256;
            int r = idx >> 6, cc = idx & 63;
            Qs[r][cc] = Qb[(size_t)(d0 + r) * W_DIM + q0 + cc];
            Ks[r][cc] = Kb[(size_t)(d0 + r) * W_DIM + k0 + cc];
        }
        __syncthreads();
        #pragma unroll
        for (int kk = 0; kk < 16; kk++) {
            float4 qa = *reinterpret_cast<const float4*>(&Qs[kk][ty * 4]);
            float4 kb = *reinterpret_cast<const float4*>(&Ks[kk][tx * 4]);
            float qv[4] = {qa.x, qa.y, qa.z, qa.w};
            float kv[4] = {kb.x, kb.y, kb.z, kb.w};
            #pragma unroll
            for (int i = 0; i < 4; i++)
                #pragma unroll
                for (int j = 0; j < 4; j++)
                    acc[i][j] += qv[i] * kv[j];
        }
        __syncthreads();
    }
    const float scale = 0.044194173824159216f;  // 1/sqrt(512)
    #pragma unroll
    for (int i = 0; i < 4; i++)
        #pragma unroll
        for (int j = 0; j < 4; j++)
            Sb[(size_t)(q0 + ty * 4 + i) * W_DIM + (k0 + tx * 4 + j)] = acc[i][j] * scale;
}

// ---------------- softmax over rows of S (warp per row) ----------------------
__global__ void __launch_bounds__(256) softmax_rows_k(float* __restrict__ S)
{
    int row = blockIdx.x * 8 + (threadIdx.x >> 5);
    int lane = threadIdx.x & 31;
    float* p = S + (size_t)row * W_DIM;
    float v[16];
    float mx = -1e30f;
    #pragma unroll
    for (int i = 0; i < 16; i++) { v[i] = p[lane + i * 32]; mx = fmaxf(mx, v[i]); }
    #pragma unroll
    for (int o = 16; o; o >>= 1) mx = fmaxf(mx, __shfl_xor_sync(0xffffffffu, mx, o));
    float sum = 0.f;
    #pragma unroll
    for (int i = 0; i < 16; i++) { v[i] = __expf(v[i] - mx); sum += v[i]; }
    #pragma unroll
    for (int o = 16; o; o >>= 1) sum += __shfl_xor_sync(0xffffffffu, sum, o);
    float inv = 1.f / sum;
    #pragma unroll
    for (int i = 0; i < 16; i++) p[lane + i * 32] = v[i] * inv;
}

// ---------------- attention output: O[d,q] = sum_k V[d,k] P[q,k] -------------
__global__ void __launch_bounds__(256) attn_out_k(
    const float* __restrict__ P, const float* __restrict__ V,
    float* __restrict__ O)
{
    int batch = blockIdx.z;
    int bc = batch >> 3, h = batch & 7;
    const float* Vb = V + ((size_t)bc * F_DIM + h * DH) * W_DIM;
    const float* Pb = P + (size_t)batch * W_DIM * W_DIM;
    float* Ob = O + ((size_t)bc * F_DIM + h * DH) * W_DIM;

    __shared__ float Vs[16][65];
    __shared__ float Ps[16][65];
    int tid = threadIdx.x;
    int tx = tid & 15, ty = tid >> 4;
    int q0 = blockIdx.x * 64;
    float acc[4][4] = {};

    for (int k0 = 0; k0 < W_DIM; k0 += 16) {
        #pragma unroll
        for (int i = 0; i < 4; i++) {
            int idx = tid + i * 256;
            int dd = idx >> 4, kc = idx & 15;
            Vs[kc][dd] = Vb[(size_t)dd * W_DIM + k0 + kc];
            Ps[kc][dd] = Pb[(size_t)(q0 + dd) * W_DIM + k0 + kc];
        }
        __syncthreads();
        #pragma unroll
        for (int kk = 0; kk < 16; kk++) {
            float av[4], bv[4];
            #pragma unroll
            for (int i = 0; i < 4; i++) av[i] = Vs[kk][ty * 4 + i];
            #pragma unroll
            for (int j = 0; j < 4; j++) bv[j] = Ps[kk][tx * 4 + j];
            #pragma unroll
            for (int i = 0; i < 4; i++)
                #pragma unroll
                for (int j = 0; j < 4; j++)
                    acc[i][j] += av[i] * bv[j];
        }
        __syncthreads();
    }
    #pragma unroll
    for (int i = 0; i < 4; i++)
        #pragma unroll
        for (int j = 0; j < 4; j++)
            Ob[(size_t)(ty * 4 + i) * W_DIM + q0 + tx * 4 + j] = acc[i][j];
}

// ---------------- host orchestration ----------------------------------------
extern "C" void kernel_launch(void* const* d_in, const int* in_sizes, int n_in,
                              void* d_out, int out_size)
{
    const float* x     = (const float*)d_in[0];
    const float* e1_pw = (const float*)d_in[1];
    const float* e1_dw = (const float*)d_in[2];
    const float* e2_pw = (const float*)d_in[3];
    const float* e2_dw = (const float*)d_in[4];
    const float* ei_pw = (const float*)d_in[5];
    const float* ei_dw = (const float*)d_in[6];
    const float* n1_w  = (const float*)d_in[7];
    const float* n1_b  = (const float*)d_in[8];
    const float* q_pw  = (const float*)d_in[9];
    const float* q_dw  = (const float*)d_in[10];
    const float* k_pw  = (const float*)d_in[11];
    const float* k_dw  = (const float*)d_in[12];
    const float* v_pw  = (const float*)d_in[13];
    const float* v_dw  = (const float*)d_in[14];
    const float* o_pw  = (const float*)d_in[15];
    const float* n2_w  = (const float*)d_in[16];
    const float* n2_b  = (const float*)d_in[17];
    const float* f1_pw = (const float*)d_in[18];
    const float* f2_pw = (const float*)d_in[19];
    const float* d1_pw = (const float*)d_in[20];
    const float* d1_dw = (const float*)d_in[21];
    const float* d2_pw = (const float*)d_in[22];
    const float* d2_dw = (const float*)d_in[23];
    const float* di_pw = (const float*)d_in[24];
    const float* di_dw = (const float*)d_in[25];
    float* out = (float*)d_out;

    float *e, *h, *q, *k, *v, *tmp, *big, *s;
    cudaGetSymbolAddress((void**)&e,   g_e);
    cudaGetSymbolAddress((void**)&h,   g_h);
    cudaGetSymbolAddress((void**)&q,   g_q);
    cudaGetSymbolAddress((void**)&k,   g_k);
    cudaGetSymbolAddress((void**)&v,   g_v);
    cudaGetSymbolAddress((void**)&tmp, g_tmp);
    cudaGetSymbolAddress((void**)&big, g_big);
    cudaGetSymbolAddress((void**)&s,   g_s);

    dim3 g512(8, 8, 4);           // M=512 GEMM
    dim3 gf1 (8, 32, 4);          // M=2048
    dim3 g1024(8, 16, 4);         // M=1024
    dim3 lnG(16, 4), lnB(32, 8);
    int mixG512  = (4 * 512 * 512) / 256;   // 4096
    int mixG1024 = (4 * 1024 * 512) / 256;  // 8192
    int ropeG    = (4 * 256 * 512) / 256;   // 2048

    // ---------------- encoder frame_block ----------------
    gemm_nn<false, false><<<g512, 256>>>(e1_pw, x, nullptr, tmp, 512, 512, 1024);
    mix_k<true, false><<<mixG512, 256>>>(tmp, e1_dw, nullptr, h, 512);
    gemm_nn<false, false><<<g512, 256>>>(e2_pw, h, nullptr, tmp, 512, 512, 512);
    mix_k<false, false><<<mixG512, 256>>>(tmp, e2_dw, nullptr, q, 512);   // z -> q
    gemm_nn<false, false><<<g512, 256>>>(ei_pw, x, nullptr, tmp, 512, 512, 1024);
    mix_k<false, true><<<mixG512, 256>>>(tmp, ei_dw, q, e, 512);          // e = id + z

    // ---------------- layers ----------------
    for (int i = 0; i < NLAYER; i++) {
        const float* qpw = q_pw + (size_t)i * 2 * 512 * 512;
        const float* kpw = k_pw + (size_t)i * 2 * 512 * 512;
        const float* vpw = v_pw + (size_t)i * 2 * 512 * 512;
        const float* opw = o_pw + (size_t)i * 2 * 512 * 512;
        const float* f1w = f1_pw + (size_t)i * 2 * 2048 * 512;
        const float* f2w = f2_pw + (size_t)i * 2 * 512 * 2048;

        frame_norm_k<<<lnG, lnB>>>(e, n1_w + (size_t)i * 1024, n1_b + (size_t)i * 1024, h);

        gemm_nn<false, false><<<g512, 256>>>(qpw, h, nullptr, tmp, 512, 512, 512);
        mix_rope_k<<<ropeG, 256>>>(tmp, q_dw + i * 4, q);
        gemm_nn<false, false><<<g512, 256>>>(kpw, h, nullptr, tmp, 512, 512, 512);
        mix_rope_k<<<ropeG, 256>>>(tmp, k_dw + i * 4, k);
        gemm_nn<false, false><<<g512, 256>>>(vpw, h, nullptr, tmp, 512, 512, 512);
        mix_k<false, false><<<mixG512, 256>>>(tmp, v_dw + i * 4, nullptr, v, 512);

        attn_scores_k<<<dim3(8, 8, 32), 256>>>(q, k, s);
        softmax_rows_k<<<2048, 256>>>(s);
        attn_out_k<<<dim3(8, 1, 32), 256>>>(s, v, h);

        gemm_nn<false, true><<<g512, 256>>>(opw, h, e, e, 512, 512, 512);   // e += O

        frame_norm_k<<<lnG, lnB>>>(e, n2_w + (size_t)i * 1024, n2_b + (size_t)i * 1024, h);
        gemm_nn<true, false><<<gf1, 256>>>(f1w, h, nullptr, big, 2048, 512, 512);
        gemm_nn<false, true><<<g512, 256>>>(f2w, big, e, e, 512, 512, 2048); // e += FFN
    }

    // ---------------- decoder frame_block ----------------
    float* ta = big;                 // (4,1024,512) scratch
    float* tb = s;                   // (4,1024,512) scratch
    float* tz = s + 2097152;         // (4,1024,512) scratch
    gemm_nn<false, false><<<g1024, 256>>>(d1_pw, e, nullptr, ta, 1024, 512, 512);
    mix_k<true, false><<<mixG1024, 256>>>(ta, d1_dw, nullptr, tb, 1024);
    gemm_nn<false, false><<<g1024, 256>>>(d2_pw, tb, nullptr, ta, 1024, 512, 1024);
    mix_k<false, false><<<mixG1024, 256>>>(ta, d2_dw, nullptr, tz, 1024);
    gemm_nn<false, false><<<g1024, 256>>>(di_pw, e, nullptr, ta, 1024, 512, 512);
    mix_k<false, true><<<mixG1024, 256>>>(ta, di_dw, tz, out, 1024);
}